// round 1
// baseline (speedup 1.0000x reference)
#include <cuda_runtime.h>
#include <math.h>

#define BB 8
#define SS 2048
#define DD 768

// Scratch (no cudaMalloc allowed): Q,K,V projections + score matrix
__device__ float g_Q[BB * SS * DD];
__device__ float g_K[BB * SS * DD];
__device__ float g_V[BB * SS * DD];
__device__ float g_P[(long long)BB * SS * SS];

// ---------------------------------------------------------------------------
// GEMM variant 1: C = scale * (A @ B^T) + bias
//   A: [M, K] row-major (lda), B: [N, K] row-major (ldb)  -> both K-contiguous
//   C: [M, N] row-major (ldc). bias may be nullptr (length N).
//   Batched via blockIdx.z with element strides sA/sB/sC.
// Tiles: 128x128x16, 256 threads, 8x8 per-thread micro-tile.
// ---------------------------------------------------------------------------
__global__ void __launch_bounds__(256, 2)
gemm_abt(const float* __restrict__ A, const float* __restrict__ Bm,
         const float* __restrict__ bias, float* __restrict__ C,
         int K, int lda, int ldb, int ldc,
         long long sA, long long sB, long long sC, float scale)
{
    const int b = blockIdx.z;
    A  += (long long)b * sA;
    Bm += (long long)b * sB;
    C  += (long long)b * sC;

    __shared__ float As[16][132];   // [k][m], padded (132*4B % 16B == 0)
    __shared__ float Bs[16][132];   // [k][n]

    const int tid = threadIdx.x;
    const int tm  = (tid >> 4) << 3;   // 0..120 step 8
    const int tn  = (tid & 15) << 3;   // 0..120 step 8
    const int m0  = blockIdx.y * 128;
    const int n0  = blockIdx.x * 128;

    float acc[8][8];
#pragma unroll
    for (int i = 0; i < 8; i++)
#pragma unroll
        for (int j = 0; j < 8; j++) acc[i][j] = 0.f;

    for (int k0 = 0; k0 < K; k0 += 16) {
        // Load A tile (128 rows x 16 cols) and B tile (128 rows x 16 cols),
        // both stored k-major (transposed) into smem.
#pragma unroll
        for (int i = 0; i < 2; i++) {
            int idx  = tid + i * 256;           // 0..511
            int row  = idx >> 2;                // 0..127
            int c4   = (idx & 3) << 2;          // 0,4,8,12
            float4 va = *(const float4*)&A[(long long)(m0 + row) * lda + k0 + c4];
            As[c4 + 0][row] = va.x; As[c4 + 1][row] = va.y;
            As[c4 + 2][row] = va.z; As[c4 + 3][row] = va.w;
            float4 vb = *(const float4*)&Bm[(long long)(n0 + row) * ldb + k0 + c4];
            Bs[c4 + 0][row] = vb.x; Bs[c4 + 1][row] = vb.y;
            Bs[c4 + 2][row] = vb.z; Bs[c4 + 3][row] = vb.w;
        }
        __syncthreads();

#pragma unroll
        for (int kk = 0; kk < 16; kk++) {
            float a[8], bb[8];
            *(float4*)&a[0]  = *(const float4*)&As[kk][tm];
            *(float4*)&a[4]  = *(const float4*)&As[kk][tm + 4];
            *(float4*)&bb[0] = *(const float4*)&Bs[kk][tn];
            *(float4*)&bb[4] = *(const float4*)&Bs[kk][tn + 4];
#pragma unroll
            for (int i = 0; i < 8; i++)
#pragma unroll
                for (int j = 0; j < 8; j++)
                    acc[i][j] = fmaf(a[i], bb[j], acc[i][j]);
        }
        __syncthreads();
    }

    float bv[8];
#pragma unroll
    for (int j = 0; j < 8; j++) bv[j] = 0.f;
    if (bias) {
        *(float4*)&bv[0] = *(const float4*)&bias[n0 + tn];
        *(float4*)&bv[4] = *(const float4*)&bias[n0 + tn + 4];
    }

#pragma unroll
    for (int i = 0; i < 8; i++) {
        float4 o0, o1;
        o0.x = acc[i][0] * scale + bv[0];
        o0.y = acc[i][1] * scale + bv[1];
        o0.z = acc[i][2] * scale + bv[2];
        o0.w = acc[i][3] * scale + bv[3];
        o1.x = acc[i][4] * scale + bv[4];
        o1.y = acc[i][5] * scale + bv[5];
        o1.z = acc[i][6] * scale + bv[6];
        o1.w = acc[i][7] * scale + bv[7];
        long long off = (long long)(m0 + tm + i) * ldc + n0 + tn;
        *(float4*)&C[off]     = o0;
        *(float4*)&C[off + 4] = o1;
    }
}

// ---------------------------------------------------------------------------
// GEMM variant 2: C = A @ B
//   A: [M, K] row-major (lda), B: [K, N] row-major (ldb), C: [M, N] (ldc).
// ---------------------------------------------------------------------------
__global__ void __launch_bounds__(256, 2)
gemm_ab(const float* __restrict__ A, const float* __restrict__ Bm,
        float* __restrict__ C,
        int K, int lda, int ldb, int ldc,
        long long sA, long long sB, long long sC)
{
    const int b = blockIdx.z;
    A  += (long long)b * sA;
    Bm += (long long)b * sB;
    C  += (long long)b * sC;

    __shared__ float As[16][132];   // [k][m]
    __shared__ float Bs[16][132];   // [k][n]

    const int tid = threadIdx.x;
    const int tm  = (tid >> 4) << 3;
    const int tn  = (tid & 15) << 3;
    const int m0  = blockIdx.y * 128;
    const int n0  = blockIdx.x * 128;

    float acc[8][8];
#pragma unroll
    for (int i = 0; i < 8; i++)
#pragma unroll
        for (int j = 0; j < 8; j++) acc[i][j] = 0.f;

    for (int k0 = 0; k0 < K; k0 += 16) {
#pragma unroll
        for (int i = 0; i < 2; i++) {
            int idx = tid + i * 256;
            // A tile: 128 rows x 16 cols, store transposed
            int arow = idx >> 2;
            int ac4  = (idx & 3) << 2;
            float4 va = *(const float4*)&A[(long long)(m0 + arow) * lda + k0 + ac4];
            As[ac4 + 0][arow] = va.x; As[ac4 + 1][arow] = va.y;
            As[ac4 + 2][arow] = va.z; As[ac4 + 3][arow] = va.w;
            // B tile: 16 rows x 128 cols, store direct
            int brow = idx >> 5;             // 0..15
            int bc4  = (idx & 31) << 2;      // 0..124 step 4
            float4 vb = *(const float4*)&Bm[(long long)(k0 + brow) * ldb + n0 + bc4];
            *(float4*)&Bs[brow][bc4] = vb;
        }
        __syncthreads();

#pragma unroll
        for (int kk = 0; kk < 16; kk++) {
            float a[8], bb[8];
            *(float4*)&a[0]  = *(const float4*)&As[kk][tm];
            *(float4*)&a[4]  = *(const float4*)&As[kk][tm + 4];
            *(float4*)&bb[0] = *(const float4*)&Bs[kk][tn];
            *(float4*)&bb[4] = *(const float4*)&Bs[kk][tn + 4];
#pragma unroll
            for (int i = 0; i < 8; i++)
#pragma unroll
                for (int j = 0; j < 8; j++)
                    acc[i][j] = fmaf(a[i], bb[j], acc[i][j]);
        }
        __syncthreads();
    }

#pragma unroll
    for (int i = 0; i < 8; i++) {
        long long off = (long long)(m0 + tm + i) * ldc + n0 + tn;
        *(float4*)&C[off]     = *(float4*)&acc[i][0];
        *(float4*)&C[off + 4] = *(float4*)&acc[i][4];
    }
}

// ---------------------------------------------------------------------------
// Row softmax over P rows of length SS (2048). One block (256 thr) per row.
// ---------------------------------------------------------------------------
__global__ void __launch_bounds__(256)
softmax_rows(float* __restrict__ P)
{
    float* p = P + (long long)blockIdx.x * SS;
    const int tid  = threadIdx.x;
    const int lane = tid & 31;
    const int wid  = tid >> 5;

    __shared__ float red[8];

    float v[8];
    float mx = -1e30f;
#pragma unroll
    for (int i = 0; i < 8; i++) {
        v[i] = p[tid + i * 256];
        mx = fmaxf(mx, v[i]);
    }
#pragma unroll
    for (int o = 16; o > 0; o >>= 1)
        mx = fmaxf(mx, __shfl_xor_sync(0xffffffffu, mx, o));
    if (lane == 0) red[wid] = mx;
    __syncthreads();
    float rmax = red[0];
#pragma unroll
    for (int i = 1; i < 8; i++) rmax = fmaxf(rmax, red[i]);
    __syncthreads();

    float s = 0.f;
#pragma unroll
    for (int i = 0; i < 8; i++) {
        v[i] = __expf(v[i] - rmax);
        s += v[i];
    }
#pragma unroll
    for (int o = 16; o > 0; o >>= 1)
        s += __shfl_xor_sync(0xffffffffu, s, o);
    if (lane == 0) red[wid] = s;
    __syncthreads();
    float tot = 0.f;
#pragma unroll
    for (int i = 0; i < 8; i++) tot += red[i];
    float inv = 1.f / tot;

#pragma unroll
    for (int i = 0; i < 8; i++)
        p[tid + i * 256] = v[i] * inv;
}

// ---------------------------------------------------------------------------
// Launch: QKV GEMMs -> scores GEMM -> softmax -> PV GEMM
// ---------------------------------------------------------------------------
extern "C" void kernel_launch(void* const* d_in, const int* in_sizes, int n_in,
                              void* d_out, int out_size)
{
    const float* Z  = (const float*)d_in[0];
    const float* Wq = (const float*)d_in[1];
    const float* bq = (const float*)d_in[2];
    const float* Wk = (const float*)d_in[3];
    const float* bk = (const float*)d_in[4];
    const float* Wv = (const float*)d_in[5];
    const float* bv = (const float*)d_in[6];
    float* out = (float*)d_out;

    float *Qp, *Kp, *Vp, *Pp;
    cudaGetSymbolAddress((void**)&Qp, g_Q);
    cudaGetSymbolAddress((void**)&Kp, g_K);
    cudaGetSymbolAddress((void**)&Vp, g_V);
    cudaGetSymbolAddress((void**)&Pp, g_P);

    dim3 blk(256);
    const long long SD = (long long)SS * DD;
    const long long SSs = (long long)SS * SS;
    const float scale = 1.0f / sqrtf((float)DD);

    // QKV projections: [B*S, D] x [D, D]^T  (M=16384, N=768, K=768)
    dim3 gq(DD / 128, (BB * SS) / 128, 1);
    gemm_abt<<<gq, blk>>>(Z, Wq, bq, Qp, DD, DD, DD, DD, 0, 0, 0, 1.0f);
    gemm_abt<<<gq, blk>>>(Z, Wk, bk, Kp, DD, DD, DD, DD, 0, 0, 0, 1.0f);
    gemm_abt<<<gq, blk>>>(Z, Wv, bv, Vp, DD, DD, DD, DD, 0, 0, 0, 1.0f);

    // Scores: per batch, Q @ K^T * scale  (M=N=2048, K=768)
    dim3 gs(SS / 128, SS / 128, BB);
    gemm_abt<<<gs, blk>>>(Qp, Kp, nullptr, Pp, DD, DD, DD, SS, SD, SD, SSs, scale);

    // Softmax over each of B*S rows
    softmax_rows<<<BB * SS, blk>>>(Pp);

    // Output: per batch, P @ V  (M=2048, N=768, K=2048)
    dim3 go(DD / 128, SS / 128, BB);
    gemm_ab<<<go, blk>>>(Pp, Vp, out, SS, SS, DD, DD, SSs, SD, SD);
}

// round 5
// speedup vs baseline: 1.5171x; 1.5171x over previous
#include <cuda_runtime.h>
#include <math.h>
#include <stdint.h>

#define BB 8
#define SS 2048
#define DD 768

// Scratch (no cudaMalloc allowed): Q,K,V projections + score matrix
__device__ float g_Q[BB * SS * DD];
__device__ float g_K[BB * SS * DD];
__device__ float g_V[BB * SS * DD];
__device__ float g_P[(long long)BB * SS * SS];

// cvt.rna.tf32.f32 requires a .b32 destination register
__device__ __forceinline__ float tf32r(float x) {
    uint32_t y;
    asm("cvt.rna.tf32.f32 %0, %1;" : "=r"(y) : "f"(x));
    return __uint_as_float(y);
}

__device__ __forceinline__ void mma_tf32(float c[4],
                                         uint32_t a0, uint32_t a1, uint32_t a2, uint32_t a3,
                                         uint32_t b0, uint32_t b1) {
    asm volatile(
        "mma.sync.aligned.m16n8k8.row.col.f32.tf32.tf32.f32 "
        "{%0,%1,%2,%3}, {%4,%5,%6,%7}, {%8,%9}, {%0,%1,%2,%3};\n"
        : "+f"(c[0]), "+f"(c[1]), "+f"(c[2]), "+f"(c[3])
        : "r"(a0), "r"(a1), "r"(a2), "r"(a3), "r"(b0), "r"(b1));
}

// ---------------------------------------------------------------------------
// tf32 tensor-core GEMM, 128x128 block tile, Kc=32, 256 threads (8 warps).
// Warp grid 4(M) x 2(N): warp tile 32x64 = 2 x 8 mma(m16n8k8) tiles.
// Two layouts:
//   NT: C = scale*(A @ B^T) + bias   A:[M,K] ld=lda, B:[N,K] ld=ldb (K-contig)
//   NN: C = A @ B                    A:[M,K] ld=lda, B:[K,N] ld=ldb (N-contig)
// Batched via blockIdx.z with element strides.
// ---------------------------------------------------------------------------
template <bool BT>
__global__ void __launch_bounds__(256, 2)
gemm_tf32(const float* __restrict__ A, const float* __restrict__ Bm,
          const float* __restrict__ bias, float* __restrict__ C,
          int K, int lda, int ldb, int ldc,
          long long sA, long long sB, long long sC, float scale)
{
    const int b = blockIdx.z;
    A  += (long long)b * sA;
    Bm += (long long)b * sB;
    C  += (long long)b * sC;

    __shared__ float As[128][33];   // [m][k]
    __shared__ float Bs[128][33];   // [n][k]

    const int tid   = threadIdx.x;
    const int lane  = tid & 31;
    const int warp  = tid >> 5;
    const int warpM = warp & 3;       // 0..3 -> 32-row slab
    const int warpN = warp >> 2;      // 0..1 -> 64-col slab
    const int grp   = lane >> 2;      // 0..7
    const int qid   = lane & 3;       // 0..3
    const int m0    = blockIdx.y * 128;
    const int n0    = blockIdx.x * 128;

    float acc[2][8][4];
#pragma unroll
    for (int mt = 0; mt < 2; mt++)
#pragma unroll
        for (int nt = 0; nt < 8; nt++)
#pragma unroll
            for (int r = 0; r < 4; r++) acc[mt][nt][r] = 0.f;

    for (int k0 = 0; k0 < K; k0 += 32) {
        // ---- fill As: 128 rows x 32 k (1024 float4 slots / 256 thr = 4 ea)
#pragma unroll
        for (int i = 0; i < 4; i++) {
            int slot = tid + i * 256;
            int row  = slot >> 3;
            int c4   = (slot & 7) << 2;
            float4 v = *(const float4*)&A[(long long)(m0 + row) * lda + k0 + c4];
            As[row][c4 + 0] = tf32r(v.x);
            As[row][c4 + 1] = tf32r(v.y);
            As[row][c4 + 2] = tf32r(v.z);
            As[row][c4 + 3] = tf32r(v.w);
        }
        // ---- fill Bs as [n][k]
        if (BT) {
#pragma unroll
            for (int i = 0; i < 4; i++) {
                int slot = tid + i * 256;
                int row  = slot >> 3;
                int c4   = (slot & 7) << 2;
                float4 v = *(const float4*)&Bm[(long long)(n0 + row) * ldb + k0 + c4];
                Bs[row][c4 + 0] = tf32r(v.x);
                Bs[row][c4 + 1] = tf32r(v.y);
                Bs[row][c4 + 2] = tf32r(v.z);
                Bs[row][c4 + 3] = tf32r(v.w);
            }
        } else {
            // B:[K,N] -> transpose into Bs[n][k]
#pragma unroll
            for (int i = 0; i < 4; i++) {
                int slot = tid + i * 256;
                int kr   = slot >> 5;            // 0..31
                int c4   = (slot & 31) << 2;     // 0..124
                float4 v = *(const float4*)&Bm[(long long)(k0 + kr) * ldb + n0 + c4];
                Bs[c4 + 0][kr] = tf32r(v.x);
                Bs[c4 + 1][kr] = tf32r(v.y);
                Bs[c4 + 2][kr] = tf32r(v.z);
                Bs[c4 + 3][kr] = tf32r(v.w);
            }
        }
        __syncthreads();

#pragma unroll
        for (int ks = 0; ks < 4; ks++) {
            const int kb = ks * 8;
            uint32_t af[2][4];
#pragma unroll
            for (int mt = 0; mt < 2; mt++) {
                int row0 = warpM * 32 + mt * 16 + grp;
                af[mt][0] = __float_as_uint(As[row0    ][kb + qid]);
                af[mt][1] = __float_as_uint(As[row0 + 8][kb + qid]);
                af[mt][2] = __float_as_uint(As[row0    ][kb + qid + 4]);
                af[mt][3] = __float_as_uint(As[row0 + 8][kb + qid + 4]);
            }
#pragma unroll
            for (int nt = 0; nt < 8; nt++) {
                int col = warpN * 64 + nt * 8 + grp;
                uint32_t b0 = __float_as_uint(Bs[col][kb + qid]);
                uint32_t b1 = __float_as_uint(Bs[col][kb + qid + 4]);
#pragma unroll
                for (int mt = 0; mt < 2; mt++)
                    mma_tf32(acc[mt][nt], af[mt][0], af[mt][1], af[mt][2], af[mt][3], b0, b1);
            }
        }
        __syncthreads();
    }

    // ---- epilogue: scale + bias, float2 stores
#pragma unroll
    for (int nt = 0; nt < 8; nt++) {
        int colc = n0 + warpN * 64 + nt * 8 + (qid << 1);
        float bv0 = 0.f, bv1 = 0.f;
        if (bias) { bv0 = bias[colc]; bv1 = bias[colc + 1]; }
#pragma unroll
        for (int mt = 0; mt < 2; mt++) {
            int row0 = m0 + warpM * 32 + mt * 16 + grp;
            float2 o0, o1;
            o0.x = acc[mt][nt][0] * scale + bv0;
            o0.y = acc[mt][nt][1] * scale + bv1;
            o1.x = acc[mt][nt][2] * scale + bv0;
            o1.y = acc[mt][nt][3] * scale + bv1;
            *(float2*)&C[(long long)row0 * ldc + colc]       = o0;
            *(float2*)&C[(long long)(row0 + 8) * ldc + colc] = o1;
        }
    }
}

// ---------------------------------------------------------------------------
// Row softmax over P rows of length SS (2048). One block (256 thr) per row.
// ---------------------------------------------------------------------------
__global__ void __launch_bounds__(256)
softmax_rows(float* __restrict__ P)
{
    float* p = P + (long long)blockIdx.x * SS;
    const int tid  = threadIdx.x;
    const int lane = tid & 31;
    const int wid  = tid >> 5;

    __shared__ float red[8];

    float v[8];
    float mx = -1e30f;
#pragma unroll
    for (int i = 0; i < 8; i++) {
        v[i] = p[tid + i * 256];
        mx = fmaxf(mx, v[i]);
    }
#pragma unroll
    for (int o = 16; o > 0; o >>= 1)
        mx = fmaxf(mx, __shfl_xor_sync(0xffffffffu, mx, o));
    if (lane == 0) red[wid] = mx;
    __syncthreads();
    float rmax = red[0];
#pragma unroll
    for (int i = 1; i < 8; i++) rmax = fmaxf(rmax, red[i]);
    __syncthreads();

    float s = 0.f;
#pragma unroll
    for (int i = 0; i < 8; i++) {
        v[i] = __expf(v[i] - rmax);
        s += v[i];
    }
#pragma unroll
    for (int o = 16; o > 0; o >>= 1)
        s += __shfl_xor_sync(0xffffffffu, s, o);
    if (lane == 0) red[wid] = s;
    __syncthreads();
    float tot = 0.f;
#pragma unroll
    for (int i = 0; i < 8; i++) tot += red[i];
    float inv = 1.f / tot;

#pragma unroll
    for (int i = 0; i < 8; i++)
        p[tid + i * 256] = v[i] * inv;
}

// ---------------------------------------------------------------------------
// Launch: QKV GEMMs -> scores GEMM -> softmax -> PV GEMM
// ---------------------------------------------------------------------------
extern "C" void kernel_launch(void* const* d_in, const int* in_sizes, int n_in,
                              void* d_out, int out_size)
{
    const float* Z  = (const float*)d_in[0];
    const float* Wq = (const float*)d_in[1];
    const float* bq = (const float*)d_in[2];
    const float* Wk = (const float*)d_in[3];
    const float* bk = (const float*)d_in[4];
    const float* Wv = (const float*)d_in[5];
    const float* bv = (const float*)d_in[6];
    float* out = (float*)d_out;

    float *Qp, *Kp, *Vp, *Pp;
    cudaGetSymbolAddress((void**)&Qp, g_Q);
    cudaGetSymbolAddress((void**)&Kp, g_K);
    cudaGetSymbolAddress((void**)&Vp, g_V);
    cudaGetSymbolAddress((void**)&Pp, g_P);

    dim3 blk(256);
    const long long SD  = (long long)SS * DD;
    const long long SSs = (long long)SS * SS;
    const float scale = 1.0f / sqrtf((float)DD);

    // QKV projections: [B*S, D] x [D, D]^T  (M=16384, N=768, K=768)
    dim3 gq(DD / 128, (BB * SS) / 128, 1);
    gemm_tf32<true><<<gq, blk>>>(Z, Wq, bq, Qp, DD, DD, DD, DD, 0, 0, 0, 1.0f);
    gemm_tf32<true><<<gq, blk>>>(Z, Wk, bk, Kp, DD, DD, DD, DD, 0, 0, 0, 1.0f);
    gemm_tf32<true><<<gq, blk>>>(Z, Wv, bv, Vp, DD, DD, DD, DD, 0, 0, 0, 1.0f);

    // Scores: per batch, Q @ K^T * scale  (M=N=2048, K=768)
    dim3 gs(SS / 128, SS / 128, BB);
    gemm_tf32<true><<<gs, blk>>>(Qp, Kp, nullptr, Pp, DD, DD, DD, SS, SD, SD, SSs, scale);

    // Softmax over each of B*S rows
    softmax_rows<<<BB * SS, blk>>>(Pp);

    // Output: per batch, P @ V  (M=2048, N=768, K=2048)
    dim3 go(DD / 128, SS / 128, BB);
    gemm_tf32<false><<<go, blk>>>(Pp, Vp, nullptr, out, SS, SS, DD, DD, SSs, SD, SD, 1.0f);
}

// round 6
// speedup vs baseline: 2.9812x; 1.9650x over previous
#include <cuda_runtime.h>
#include <math.h>
#include <stdint.h>

#define BB 8
#define SS 2048
#define DD 768

// Scratch (no cudaMalloc allowed): Q,K,V projections + score matrix
__device__ float g_Q[BB * SS * DD];
__device__ float g_K[BB * SS * DD];
__device__ float g_V[BB * SS * DD];
__device__ float g_P[(long long)BB * SS * SS];

// cvt.rna.tf32.f32 requires a .b32 destination register
__device__ __forceinline__ float tf32r(float x) {
    uint32_t y;
    asm("cvt.rna.tf32.f32 %0, %1;" : "=r"(y) : "f"(x));
    return __uint_as_float(y);
}

__device__ __forceinline__ void mma_tf32(float c[4],
                                         uint32_t a0, uint32_t a1, uint32_t a2, uint32_t a3,
                                         uint32_t b0, uint32_t b1) {
    asm volatile(
        "mma.sync.aligned.m16n8k8.row.col.f32.tf32.tf32.f32 "
        "{%0,%1,%2,%3}, {%4,%5,%6,%7}, {%8,%9}, {%0,%1,%2,%3};\n"
        : "+f"(c[0]), "+f"(c[1]), "+f"(c[2]), "+f"(c[3])
        : "r"(a0), "r"(a1), "r"(a2), "r"(a3), "r"(b0), "r"(b1));
}

__device__ __forceinline__ void cpasync16(void* dst, const void* src) {
    uint32_t d = (uint32_t)__cvta_generic_to_shared(dst);
    asm volatile("cp.async.cg.shared.global [%0], [%1], 16;\n" :: "r"(d), "l"(src));
}

// ---------------------------------------------------------------------------
// tf32 tensor-core GEMM, 128x128 block tile, Kc=16, 2-stage cp.async pipeline,
// 256 threads (8 warps). Warp grid 4(M) x 2(N): warp tile 32x64 = 2x8 mma tiles.
//   BT=1 (NT): C = scale*(A @ B^T) + bias   A:[M,K], B:[N,K]  (K-contig)
//   BT=0 (NN): C = A @ B                    A:[M,K], B:[K,N]  (N-contig)
// CVT: round operands to tf32 when loading fragments (inputs are raw fp32).
// RND: round outputs to tf32 in epilogue (so consumers can skip CVT).
// Smem padding chosen conflict-free: As/BsBT [128][20], BsNN [16][136].
// ---------------------------------------------------------------------------
template <bool BT, bool CVT, bool RND>
__global__ void __launch_bounds__(256, 2)
gemm_tf32(const float* __restrict__ A, const float* __restrict__ Bm,
          const float* __restrict__ bias, float* __restrict__ C,
          int K, int lda, int ldb, int ldc,
          long long sA, long long sB, long long sC, float scale)
{
    const int b = blockIdx.z;
    A  += (long long)b * sA;
    Bm += (long long)b * sB;
    C  += (long long)b * sC;

    __shared__ float As[2][128][20];                 // [stage][m][k]
    __shared__ float Bs[2][BT ? 128 * 20 : 16 * 136];

    const int tid   = threadIdx.x;
    const int lane  = tid & 31;
    const int warp  = tid >> 5;
    const int warpM = warp & 3;       // 0..3 -> 32-row slab
    const int warpN = warp >> 2;      // 0..1 -> 64-col slab
    const int grp   = lane >> 2;      // 0..7
    const int qid   = lane & 3;       // 0..3
    const int m0    = blockIdx.y * 128;
    const int n0    = blockIdx.x * 128;

    float acc[2][8][4];
#pragma unroll
    for (int mt = 0; mt < 2; mt++)
#pragma unroll
        for (int nt = 0; nt < 8; nt++)
#pragma unroll
            for (int r = 0; r < 4; r++) acc[mt][nt][r] = 0.f;

    // ---- async stage loader: A 128x16, B 128x16 (BT) or 16x128 (NN)
    auto load_stage = [&](int k0, int s) {
#pragma unroll
        for (int i = 0; i < 2; i++) {
            int slot = tid + i * 256;            // 0..511
            int row  = slot >> 2;                // 0..127
            int c4   = (slot & 3) << 2;          // 0,4,8,12
            cpasync16(&As[s][row][c4], &A[(long long)(m0 + row) * lda + k0 + c4]);
        }
        if (BT) {
            float (*bs)[20] = (float (*)[20])Bs[s];
#pragma unroll
            for (int i = 0; i < 2; i++) {
                int slot = tid + i * 256;
                int row  = slot >> 2;
                int c4   = (slot & 3) << 2;
                cpasync16(&bs[row][c4], &Bm[(long long)(n0 + row) * ldb + k0 + c4]);
            }
        } else {
            float (*bs)[136] = (float (*)[136])Bs[s];
#pragma unroll
            for (int i = 0; i < 2; i++) {
                int slot = tid + i * 256;
                int kr   = slot >> 5;            // 0..15
                int c4   = (slot & 31) << 2;     // 0..124
                cpasync16(&bs[kr][c4], &Bm[(long long)(k0 + kr) * ldb + n0 + c4]);
            }
        }
        asm volatile("cp.async.commit_group;\n" ::);
    };

    const int NK = K >> 4;
    load_stage(0, 0);

    for (int it = 0; it < NK; it++) {
        if (it + 1 < NK) {
            load_stage((it + 1) << 4, (it + 1) & 1);
            asm volatile("cp.async.wait_group 1;\n" ::);
        } else {
            asm volatile("cp.async.wait_group 0;\n" ::);
        }
        __syncthreads();

        const int s = it & 1;
        const float (*as)[20] = As[s];
        const float (*bsT)[20]  = (const float (*)[20])Bs[s];
        const float (*bsN)[136] = (const float (*)[136])Bs[s];

#pragma unroll
        for (int ks = 0; ks < 2; ks++) {
            const int kb = ks * 8;
            uint32_t af[2][4];
#pragma unroll
            for (int mt = 0; mt < 2; mt++) {
                int row0 = warpM * 32 + mt * 16 + grp;
                float a0 = as[row0    ][kb + qid];
                float a1 = as[row0 + 8][kb + qid];
                float a2 = as[row0    ][kb + qid + 4];
                float a3 = as[row0 + 8][kb + qid + 4];
                if (CVT) { a0 = tf32r(a0); a1 = tf32r(a1); a2 = tf32r(a2); a3 = tf32r(a3); }
                af[mt][0] = __float_as_uint(a0);
                af[mt][1] = __float_as_uint(a1);
                af[mt][2] = __float_as_uint(a2);
                af[mt][3] = __float_as_uint(a3);
            }
#pragma unroll
            for (int nt = 0; nt < 8; nt++) {
                int col = warpN * 64 + nt * 8 + grp;
                float fb0, fb1;
                if (BT) { fb0 = bsT[col][kb + qid]; fb1 = bsT[col][kb + qid + 4]; }
                else    { fb0 = bsN[kb + qid][col]; fb1 = bsN[kb + qid + 4][col]; }
                if (CVT) { fb0 = tf32r(fb0); fb1 = tf32r(fb1); }
                uint32_t b0 = __float_as_uint(fb0);
                uint32_t b1 = __float_as_uint(fb1);
#pragma unroll
                for (int mt = 0; mt < 2; mt++)
                    mma_tf32(acc[mt][nt], af[mt][0], af[mt][1], af[mt][2], af[mt][3], b0, b1);
            }
        }
        __syncthreads();
    }

    // ---- epilogue: scale + bias (+ optional tf32 rounding), float2 stores
#pragma unroll
    for (int nt = 0; nt < 8; nt++) {
        int colc = n0 + warpN * 64 + nt * 8 + (qid << 1);
        float bv0 = 0.f, bv1 = 0.f;
        if (bias) { bv0 = bias[colc]; bv1 = bias[colc + 1]; }
#pragma unroll
        for (int mt = 0; mt < 2; mt++) {
            int row0 = m0 + warpM * 32 + mt * 16 + grp;
            float2 o0, o1;
            o0.x = acc[mt][nt][0] * scale + bv0;
            o0.y = acc[mt][nt][1] * scale + bv1;
            o1.x = acc[mt][nt][2] * scale + bv0;
            o1.y = acc[mt][nt][3] * scale + bv1;
            if (RND) {
                o0.x = tf32r(o0.x); o0.y = tf32r(o0.y);
                o1.x = tf32r(o1.x); o1.y = tf32r(o1.y);
            }
            *(float2*)&C[(long long)row0 * ldc + colc]       = o0;
            *(float2*)&C[(long long)(row0 + 8) * ldc + colc] = o1;
        }
    }
}

// ---------------------------------------------------------------------------
// Row softmax over P rows of length SS (2048). One block (256 thr) per row.
// Output rounded to tf32 so the PV GEMM can skip per-element cvt.
// ---------------------------------------------------------------------------
__global__ void __launch_bounds__(256)
softmax_rows(float* __restrict__ P)
{
    float* p = P + (long long)blockIdx.x * SS;
    const int tid  = threadIdx.x;
    const int lane = tid & 31;
    const int wid  = tid >> 5;

    __shared__ float red[8];

    float v[8];
    float mx = -1e30f;
#pragma unroll
    for (int i = 0; i < 8; i++) {
        v[i] = p[tid + i * 256];
        mx = fmaxf(mx, v[i]);
    }
#pragma unroll
    for (int o = 16; o > 0; o >>= 1)
        mx = fmaxf(mx, __shfl_xor_sync(0xffffffffu, mx, o));
    if (lane == 0) red[wid] = mx;
    __syncthreads();
    float rmax = red[0];
#pragma unroll
    for (int i = 1; i < 8; i++) rmax = fmaxf(rmax, red[i]);
    __syncthreads();

    float s = 0.f;
#pragma unroll
    for (int i = 0; i < 8; i++) {
        v[i] = __expf(v[i] - rmax);
        s += v[i];
    }
#pragma unroll
    for (int o = 16; o > 0; o >>= 1)
        s += __shfl_xor_sync(0xffffffffu, s, o);
    if (lane == 0) red[wid] = s;
    __syncthreads();
    float tot = 0.f;
#pragma unroll
    for (int i = 0; i < 8; i++) tot += red[i];
    float inv = 1.f / tot;

#pragma unroll
    for (int i = 0; i < 8; i++)
        p[tid + i * 256] = tf32r(v[i] * inv);
}

// ---------------------------------------------------------------------------
// Launch: QKV GEMMs -> scores GEMM -> softmax -> PV GEMM
// ---------------------------------------------------------------------------
extern "C" void kernel_launch(void* const* d_in, const int* in_sizes, int n_in,
                              void* d_out, int out_size)
{
    const float* Z  = (const float*)d_in[0];
    const float* Wq = (const float*)d_in[1];
    const float* bq = (const float*)d_in[2];
    const float* Wk = (const float*)d_in[3];
    const float* bk = (const float*)d_in[4];
    const float* Wv = (const float*)d_in[5];
    const float* bv = (const float*)d_in[6];
    float* out = (float*)d_out;

    float *Qp, *Kp, *Vp, *Pp;
    cudaGetSymbolAddress((void**)&Qp, g_Q);
    cudaGetSymbolAddress((void**)&Kp, g_K);
    cudaGetSymbolAddress((void**)&Vp, g_V);
    cudaGetSymbolAddress((void**)&Pp, g_P);

    dim3 blk(256);
    const long long SD  = (long long)SS * DD;
    const long long SSs = (long long)SS * SS;
    const float scale = 1.0f / sqrtf((float)DD);

    // QKV projections (raw fp32 in -> tf32-rounded out): M=16384, N=768, K=768
    dim3 gq(DD / 128, (BB * SS) / 128, 1);
    gemm_tf32<true,  true,  true ><<<gq, blk>>>(Z, Wq, bq, Qp, DD, DD, DD, DD, 0, 0, 0, 1.0f);
    gemm_tf32<true,  true,  true ><<<gq, blk>>>(Z, Wk, bk, Kp, DD, DD, DD, DD, 0, 0, 0, 1.0f);
    gemm_tf32<true,  true,  true ><<<gq, blk>>>(Z, Wv, bv, Vp, DD, DD, DD, DD, 0, 0, 0, 1.0f);

    // Scores: per batch, Q @ K^T * scale (operands pre-rounded): M=N=2048, K=768
    dim3 gs(SS / 128, SS / 128, BB);
    gemm_tf32<true,  false, false><<<gs, blk>>>(Qp, Kp, nullptr, Pp, DD, DD, DD, SS, SD, SD, SSs, scale);

    // Softmax over each of B*S rows (rounds P to tf32 on store)
    softmax_rows<<<BB * SS, blk>>>(Pp);

    // Output: per batch, P @ V (operands pre-rounded): M=2048, N=768, K=2048
    dim3 go(DD / 128, SS / 128, BB);
    gemm_tf32<false, false, false><<<go, blk>>>(Pp, Vp, nullptr, out, SS, SS, DD, DD, SSs, SD, SD, 1.0f);
}

// round 8
// speedup vs baseline: 3.1507x; 1.0569x over previous
#include <cuda_runtime.h>
#include <math.h>
#include <stdint.h>

#define BB 8
#define SS 2048
#define DD 768

// Scratch (no cudaMalloc allowed): Q,K projections, transposed V, score matrix
__device__ float g_Q[BB * SS * DD];
__device__ float g_K[BB * SS * DD];
__device__ float g_Vt[BB * SS * DD];   // layout [e][b*s]  (ld = BB*SS)
__device__ float g_P[(long long)BB * SS * SS];

// cvt.rna.tf32.f32 requires a .b32 destination register
__device__ __forceinline__ float tf32r(float x) {
    uint32_t y;
    asm("cvt.rna.tf32.f32 %0, %1;" : "=r"(y) : "f"(x));
    return __uint_as_float(y);
}
__device__ __forceinline__ uint32_t tf32u(uint32_t x) {
    uint32_t y;
    asm("cvt.rna.tf32.f32 %0, %1;" : "=r"(y) : "f"(__uint_as_float(x)));
    return y;
}

__device__ __forceinline__ void mma_tf32(float c[4],
                                         uint32_t a0, uint32_t a1, uint32_t a2, uint32_t a3,
                                         uint32_t b0, uint32_t b1) {
    asm volatile(
        "mma.sync.aligned.m16n8k8.row.col.f32.tf32.tf32.f32 "
        "{%0,%1,%2,%3}, {%4,%5,%6,%7}, {%8,%9}, {%0,%1,%2,%3};\n"
        : "+f"(c[0]), "+f"(c[1]), "+f"(c[2]), "+f"(c[3])
        : "r"(a0), "r"(a1), "r"(a2), "r"(a3), "r"(b0), "r"(b1));
}

// ldmatrix x4 of 8x8 b16 matrices == four 8x4 tf32 blocks; thread t receives
// tf32 element (t/4, t%4) of each matrix -> exact tf32 mma fragment layout.
__device__ __forceinline__ void ldsm4(uint32_t& r0, uint32_t& r1, uint32_t& r2, uint32_t& r3,
                                      uint32_t addr) {
    asm volatile("ldmatrix.sync.aligned.m8n8.x4.shared.b16 {%0,%1,%2,%3}, [%4];\n"
                 : "=r"(r0), "=r"(r1), "=r"(r2), "=r"(r3) : "r"(addr));
}

__device__ __forceinline__ void cpasync16(uint32_t dst, const void* src) {
    asm volatile("cp.async.cg.shared.global [%0], [%1], 16;\n" :: "r"(dst), "l"(src));
}

// ---------------------------------------------------------------------------
// tf32 tensor-core NT GEMM: C = scale*(A @ B^T) + bias
//   A:[M,K] ld=lda, B:[N,K] ld=ldb (both K-contiguous), C:[M,N] ld=ldc.
// 128x128 block tile, Kc=16, 2-stage cp.async pipeline, 256 threads (8 warps),
// warp tile 32(M)x64(N) = 2x8 m16n8k8 mma tiles, fragments via ldmatrix.x4.b16.
// CVT: round operands to tf32 at consume. RND: round outputs to tf32.
// BROW: bias indexed by M-row (for the transposed-V projection) else by N-col.
// Smem [128][20]: ldmatrix rows at 80B stride -> all 32 banks once, conflict-free.
// ---------------------------------------------------------------------------
template <bool CVT, bool RND, bool BROW>
__global__ void __launch_bounds__(256, 2)
gemm_nt(const float* __restrict__ A, const float* __restrict__ Bm,
        const float* __restrict__ bias, float* __restrict__ C,
        int K, int lda, int ldb, int ldc,
        long long sA, long long sB, long long sC, float scale)
{
    const int b = blockIdx.z;
    A  += (long long)b * sA;
    Bm += (long long)b * sB;
    C  += (long long)b * sC;

    __shared__ __align__(16) float As[2][128][20];   // [stage][m][k]
    __shared__ __align__(16) float Bs[2][128][20];   // [stage][n][k]

    const int tid   = threadIdx.x;
    const int lane  = tid & 31;
    const int warp  = tid >> 5;
    const int warpM = warp & 3;       // 0..3 -> 32-row slab
    const int warpN = warp >> 2;      // 0..1 -> 64-col slab
    const int grp   = lane >> 2;      // 0..7
    const int qid   = lane & 3;       // 0..3
    const int m0    = blockIdx.y * 128;
    const int n0    = blockIdx.x * 128;

    // ldmatrix per-thread row assignment: local row + matrix select
    const int local = lane & 7;
    const int sel   = lane >> 3;      // 0..3
    // A: matrices ordered (row-lo,k-lo),(row-hi,k-lo),(row-lo,k-hi),(row-hi,k-hi)
    const int rowA = warpM * 32 + ((sel & 1) << 3) + local;
    const int kcA  = (sel >> 1) << 2;
    // B: matrices ordered (n-lo,k-lo),(n-lo,k-hi),(n-hi,k-lo),(n-hi,k-hi)
    const int rowB = warpN * 64 + ((sel >> 1) << 3) + local;
    const int kcB  = (sel & 1) << 2;

    const uint32_t as_base = (uint32_t)__cvta_generic_to_shared(&As[0][0][0]);
    const uint32_t bs_base = (uint32_t)__cvta_generic_to_shared(&Bs[0][0][0]);
    const uint32_t STAGE   = 128 * 20 * 4;

    float acc[2][8][4];
#pragma unroll
    for (int mt = 0; mt < 2; mt++)
#pragma unroll
        for (int nt = 0; nt < 8; nt++)
#pragma unroll
            for (int r = 0; r < 4; r++) acc[mt][nt][r] = 0.f;

    // ---- async stage loader: A 128x16, B 128x16 (both K-contiguous)
    auto load_stage = [&](int k0, int s) {
#pragma unroll
        for (int i = 0; i < 2; i++) {
            int slot = tid + i * 256;            // 0..511
            int row  = slot >> 2;                // 0..127
            int c4   = (slot & 3) << 2;          // 0,4,8,12
            cpasync16(as_base + s * STAGE + (row * 20 + c4) * 4,
                      &A[(long long)(m0 + row) * lda + k0 + c4]);
            cpasync16(bs_base + s * STAGE + (row * 20 + c4) * 4,
                      &Bm[(long long)(n0 + row) * ldb + k0 + c4]);
        }
        asm volatile("cp.async.commit_group;\n" ::);
    };

    const int NK = K >> 4;
    load_stage(0, 0);

    for (int it = 0; it < NK; it++) {
        if (it + 1 < NK) {
            load_stage((it + 1) << 4, (it + 1) & 1);
            asm volatile("cp.async.wait_group 1;\n" ::);
        } else {
            asm volatile("cp.async.wait_group 0;\n" ::);
        }
        __syncthreads();

        const uint32_t as_s = as_base + (it & 1) * STAGE;
        const uint32_t bs_s = bs_base + (it & 1) * STAGE;

#pragma unroll
        for (int ks = 0; ks < 2; ks++) {
            const int kb = ks * 8;
            uint32_t af[2][4];
#pragma unroll
            for (int mt = 0; mt < 2; mt++) {
                uint32_t addr = as_s + (((rowA + mt * 16) * 20) + kb + kcA) * 4;
                ldsm4(af[mt][0], af[mt][1], af[mt][2], af[mt][3], addr);
                if (CVT) {
                    af[mt][0] = tf32u(af[mt][0]); af[mt][1] = tf32u(af[mt][1]);
                    af[mt][2] = tf32u(af[mt][2]); af[mt][3] = tf32u(af[mt][3]);
                }
            }
#pragma unroll
            for (int p = 0; p < 4; p++) {       // nt pair p -> nt=2p, 2p+1
                uint32_t b0, b1, b2, b3;
                uint32_t addr = bs_s + (((rowB + p * 16) * 20) + kb + kcB) * 4;
                ldsm4(b0, b1, b2, b3, addr);
                if (CVT) { b0 = tf32u(b0); b1 = tf32u(b1); b2 = tf32u(b2); b3 = tf32u(b3); }
#pragma unroll
                for (int mt = 0; mt < 2; mt++) {
                    mma_tf32(acc[mt][2 * p],     af[mt][0], af[mt][1], af[mt][2], af[mt][3], b0, b1);
                    mma_tf32(acc[mt][2 * p + 1], af[mt][0], af[mt][1], af[mt][2], af[mt][3], b2, b3);
                }
            }
        }
        __syncthreads();
    }

    // ---- epilogue: scale + bias (+ optional tf32 rounding), float2 stores
#pragma unroll
    for (int nt = 0; nt < 8; nt++) {
        int colc = n0 + warpN * 64 + nt * 8 + (qid << 1);
        float bc0 = 0.f, bc1 = 0.f;
        if (bias && !BROW) { bc0 = bias[colc]; bc1 = bias[colc + 1]; }
#pragma unroll
        for (int mt = 0; mt < 2; mt++) {
            int row0 = m0 + warpM * 32 + mt * 16 + grp;
            float br0 = 0.f, br1 = 0.f;
            if (bias && BROW) { br0 = bias[row0]; br1 = bias[row0 + 8]; }
            float2 o0, o1;
            o0.x = acc[mt][nt][0] * scale + (BROW ? br0 : bc0);
            o0.y = acc[mt][nt][1] * scale + (BROW ? br0 : bc1);
            o1.x = acc[mt][nt][2] * scale + (BROW ? br1 : bc0);
            o1.y = acc[mt][nt][3] * scale + (BROW ? br1 : bc1);
            if (RND) {
                o0.x = tf32r(o0.x); o0.y = tf32r(o0.y);
                o1.x = tf32r(o1.x); o1.y = tf32r(o1.y);
            }
            *(float2*)&C[(long long)row0 * ldc + colc]       = o0;
            *(float2*)&C[(long long)(row0 + 8) * ldc + colc] = o1;
        }
    }
}

// ---------------------------------------------------------------------------
// Row softmax over P rows of length SS (2048). One block (256 thr) per row.
// Output rounded to tf32 so the PV GEMM can skip per-element cvt.
// ---------------------------------------------------------------------------
__global__ void __launch_bounds__(256)
softmax_rows(float* __restrict__ P)
{
    float* p = P + (long long)blockIdx.x * SS;
    const int tid  = threadIdx.x;
    const int lane = tid & 31;
    const int wid  = tid >> 5;

    __shared__ float red[8];

    float v[8];
    float mx = -1e30f;
#pragma unroll
    for (int i = 0; i < 8; i++) {
        v[i] = p[tid + i * 256];
        mx = fmaxf(mx, v[i]);
    }
#pragma unroll
    for (int o = 16; o > 0; o >>= 1)
        mx = fmaxf(mx, __shfl_xor_sync(0xffffffffu, mx, o));
    if (lane == 0) red[wid] = mx;
    __syncthreads();
    float rmax = red[0];
#pragma unroll
    for (int i = 1; i < 8; i++) rmax = fmaxf(rmax, red[i]);
    __syncthreads();

    float s = 0.f;
#pragma unroll
    for (int i = 0; i < 8; i++) {
        v[i] = __expf(v[i] - rmax);
        s += v[i];
    }
#pragma unroll
    for (int o = 16; o > 0; o >>= 1)
        s += __shfl_xor_sync(0xffffffffu, s, o);
    if (lane == 0) red[wid] = s;
    __syncthreads();
    float tot = 0.f;
#pragma unroll
    for (int i = 0; i < 8; i++) tot += red[i];
    float inv = 1.f / tot;

#pragma unroll
    for (int i = 0; i < 8; i++)
        p[tid + i * 256] = tf32r(v[i] * inv);
}

// ---------------------------------------------------------------------------
// Launch: Q,K projections + transposed V projection -> scores -> softmax -> PV
// ---------------------------------------------------------------------------
extern "C" void kernel_launch(void* const* d_in, const int* in_sizes, int n_in,
                              void* d_out, int out_size)
{
    const float* Z  = (const float*)d_in[0];
    const float* Wq = (const float*)d_in[1];
    const float* bq = (const float*)d_in[2];
    const float* Wk = (const float*)d_in[3];
    const float* bk = (const float*)d_in[4];
    const float* Wv = (const float*)d_in[5];
    const float* bv = (const float*)d_in[6];
    float* out = (float*)d_out;

    float *Qp, *Kp, *Vtp, *Pp;
    cudaGetSymbolAddress((void**)&Qp,  g_Q);
    cudaGetSymbolAddress((void**)&Kp,  g_K);
    cudaGetSymbolAddress((void**)&Vtp, g_Vt);
    cudaGetSymbolAddress((void**)&Pp,  g_P);

    dim3 blk(256);
    const long long SD  = (long long)SS * DD;
    const long long SSs = (long long)SS * SS;
    const int BS = BB * SS;
    const float scale = 1.0f / sqrtf((float)DD);

    // Q,K projections: [B*S, D] x [D, D]^T  (M=16384, N=768, K=768)
    dim3 gq(DD / 128, BS / 128, 1);
    gemm_nt<true, true, false><<<gq, blk>>>(Z, Wq, bq, Qp, DD, DD, DD, DD, 0, 0, 0, 1.0f);
    gemm_nt<true, true, false><<<gq, blk>>>(Z, Wk, bk, Kp, DD, DD, DD, DD, 0, 0, 0, 1.0f);

    // Transposed V projection: Vt = Wv @ Z^T  (M=768, N=16384, K=768),
    // bias applied per M-row; output layout Vt[e][b*s], ld = B*S.
    dim3 gv(BS / 128, DD / 128, 1);
    gemm_nt<true, true, true ><<<gv, blk>>>(Wv, Z, bv, Vtp, DD, DD, DD, BS, 0, 0, 0, 1.0f);

    // Scores: per batch, Q @ K^T * scale (operands pre-rounded): M=N=2048, K=768
    dim3 gs(SS / 128, SS / 128, BB);
    gemm_nt<false, false, false><<<gs, blk>>>(Qp, Kp, nullptr, Pp, DD, DD, DD, SS, SD, SD, SSs, scale);

    // Softmax over each of B*S rows (rounds P to tf32 on store)
    softmax_rows<<<BS, blk>>>(Pp);

    // Output: per batch, P @ Vt^T (NT): M=2048, N=768, K=2048
    // B = Vt[e][b*s]: ldb = B*S, batch stride = SS.
    dim3 go(DD / 128, SS / 128, BB);
    gemm_nt<false, false, false><<<go, blk>>>(Pp, Vtp, nullptr, out, SS, SS, BS, DD, SSs, SS, SD, 1.0f);
}